// round 1
// baseline (speedup 1.0000x reference)
#include <cuda_runtime.h>
#include <cuda_bf16.h>

// EEBasis: out[n, 0, s] = exp(-|zeta[s]| * sqrt(diffs[n, center_idxs[s], 3]))
// N = 262144 rows, 64 centers (float4 each: dx,dy,dz,r2), 256 shells (4/center).
//
// Shells are center-grouped (center_idxs = repeat(arange(64), 4)), so:
//   float4-linear input index  (n*64 + g)  ==  float4-linear output index.
// Each thread: 1x LDG.128 (diffs), 1x LDG.128 (zetas, L1-hit), 1x LDG.32
// (center idx, L1-hit), 1 sqrt, 4 exp, 1x STG.128. Fully coalesced both ways.

__global__ void __launch_bounds__(256) eebasis_kernel(
    const float4* __restrict__ diffs,      // [N, 64] float4
    const float4* __restrict__ zetas4,     // [64] float4 (256 zetas)
    const int*    __restrict__ center_idxs,// [256]
    float4*       __restrict__ out,        // [N, 64] float4 (= [N,256] f32)
    int total)                              // N * 64
{
    int idx = blockIdx.x * blockDim.x + threadIdx.x;
    if (idx >= total) return;

    int g = idx & 63;                 // shell-group = output float4 column
    int n = idx >> 6;                 // row

    // center for this shell group (L1-resident 1KB table; == g for this data,
    // but honor the gather semantics)
    int c = __ldg(&center_idxs[4 * g]);

    float4 d = __ldg(&diffs[n * 64 + c]);
    float  r = sqrtf(d.w);

    float4 z = __ldg(&zetas4[g]);     // L1-resident 1KB table

    float4 o;
    o.x = __expf(-fabsf(z.x) * r);
    o.y = __expf(-fabsf(z.y) * r);
    o.z = __expf(-fabsf(z.z) * r);
    o.w = __expf(-fabsf(z.w) * r);

    out[idx] = o;
}

extern "C" void kernel_launch(void* const* d_in, const int* in_sizes, int n_in,
                              void* d_out, int out_size)
{
    const float* diffs       = (const float*)d_in[0];  // [N, 64, 4] f32
    const float* zetas       = (const float*)d_in[1];  // [256] f32
    const int*   center_idxs = (const int*)  d_in[2];  // [256] i32

    int n_rows = in_sizes[0] / (64 * 4);
    int total  = n_rows * 64;

    int threads = 256;
    int blocks  = (total + threads - 1) / threads;

    eebasis_kernel<<<blocks, threads>>>(
        (const float4*)diffs,
        (const float4*)zetas,
        center_idxs,
        (float4*)d_out,
        total);
}

// round 2
// speedup vs baseline: 1.0653x; 1.0653x over previous
#include <cuda_runtime.h>
#include <cuda_bf16.h>

// EEBasis: out[n, 0, s] = exp(-|zeta[s]| * sqrt(diffs[n, center_idxs[s], 3]))
// N = 262144 rows, 64 centers (float4: dx,dy,dz,r2), 256 shells (4/center).
//
// Shells are center-grouped, so float4-linear input index == float4-linear
// output index. Strictly streaming (single-touch) on both 256 MB streams:
//  - __ldcs on diffs (evict-first: don't pollute L2)
//  - __stcs on out   (streaming store)
//  - 2 items per thread, split total/2 apart: both coalesced, loads
//    front-batched for MLP.

__global__ void __launch_bounds__(256) eebasis_kernel(
    const float4* __restrict__ diffs,       // [N*64] float4
    const float4* __restrict__ zetas4,      // [64] float4 (256 zetas)
    const int*    __restrict__ center_idxs, // [256]
    float4*       __restrict__ out,         // [N*64] float4
    int half)                                // total/2
{
    int i0 = blockIdx.x * blockDim.x + threadIdx.x;
    if (i0 >= half) return;
    int i1 = i0 + half;

    int g0 = i0 & 63, n0 = i0 >> 6;
    int g1 = i1 & 63, n1 = i1 >> 6;

    // gather table (1KB, L1-resident)
    int c0 = __ldg(&center_idxs[4 * g0]);
    int c1 = __ldg(&center_idxs[4 * g1]);

    // front-batched streaming loads
    float4 d0 = __ldcs(&diffs[n0 * 64 + c0]);
    float4 d1 = __ldcs(&diffs[n1 * 64 + c1]);

    float4 z0 = __ldg(&zetas4[g0]);   // 1KB table, L1-resident
    float4 z1 = __ldg(&zetas4[g1]);

    float r0 = sqrtf(d0.w);
    float r1 = sqrtf(d1.w);

    float4 o0, o1;
    o0.x = __expf(-fabsf(z0.x) * r0);
    o0.y = __expf(-fabsf(z0.y) * r0);
    o0.z = __expf(-fabsf(z0.z) * r0);
    o0.w = __expf(-fabsf(z0.w) * r0);

    o1.x = __expf(-fabsf(z1.x) * r1);
    o1.y = __expf(-fabsf(z1.y) * r1);
    o1.z = __expf(-fabsf(z1.z) * r1);
    o1.w = __expf(-fabsf(z1.w) * r1);

    __stcs(&out[i0], o0);
    __stcs(&out[i1], o1);
}

extern "C" void kernel_launch(void* const* d_in, const int* in_sizes, int n_in,
                              void* d_out, int out_size)
{
    const float* diffs       = (const float*)d_in[0];  // [N, 64, 4] f32
    const float* zetas       = (const float*)d_in[1];  // [256] f32
    const int*   center_idxs = (const int*)  d_in[2];  // [256] i32

    int n_rows = in_sizes[0] / (64 * 4);
    int total  = n_rows * 64;
    int half   = total / 2;   // N is a power of two; total even

    int threads = 256;
    int blocks  = (half + threads - 1) / threads;

    eebasis_kernel<<<blocks, threads>>>(
        (const float4*)diffs,
        (const float4*)zetas,
        center_idxs,
        (float4*)d_out,
        half);
}